// round 1
// baseline (speedup 1.0000x reference)
#include <cuda_runtime.h>

// out[b, f] = x0[b, f] * sum_k(x[b, k] * w[k]) + bias[f] + x[b, f]
// B = 16384 rows, F = 2048 cols, fp32.
// One CTA per row; 256 threads; each thread owns 8 columns (2 x float4).
// x row is loaded once into registers, used for both the dot product and
// the final elementwise output -> every HBM byte touched exactly once.

#define F_DIM 2048
#define VEC_PER_ROW (F_DIM / 4)   // 512 float4
#define THREADS 256

__global__ __launch_bounds__(THREADS, 8)
void cross_fused_kernel(const float4* __restrict__ x0,
                        const float4* __restrict__ x,
                        const float4* __restrict__ w,
                        const float4* __restrict__ bias,
                        float4* __restrict__ out)
{
    const int row = blockIdx.x;
    const int tid = threadIdx.x;
    const long base = (long)row * VEC_PER_ROW;

    // Each thread handles vector lanes tid and tid+256 of this row.
    const int i0 = tid;
    const int i1 = tid + THREADS;

    // Load x row (held in registers for the write-back phase).
    float4 xa = x[base + i0];
    float4 xb = x[base + i1];

    // Weights: broadcast across all rows, L2/L1 resident.
    float4 wa = w[i0];
    float4 wb = w[i1];

    // Per-thread partial dot.
    float s = xa.x * wa.x + xa.y * wa.y + xa.z * wa.z + xa.w * wa.w
            + xb.x * wb.x + xb.y * wb.y + xb.z * wb.z + xb.w * wb.w;

    // Warp reduce.
    #pragma unroll
    for (int off = 16; off > 0; off >>= 1)
        s += __shfl_xor_sync(0xFFFFFFFFu, s, off);

    // Cross-warp reduce (8 warps).
    __shared__ float warp_sums[THREADS / 32];
    __shared__ float row_sum;
    const int lane = tid & 31;
    const int warp = tid >> 5;
    if (lane == 0) warp_sums[warp] = s;
    __syncthreads();
    if (warp == 0) {
        float v = (lane < (THREADS / 32)) ? warp_sums[lane] : 0.0f;
        #pragma unroll
        for (int off = 4; off > 0; off >>= 1)
            v += __shfl_xor_sync(0xFFFFFFFFu, v, off);
        if (lane == 0) row_sum = v;
    }
    __syncthreads();
    const float xw = row_sum;

    // Write-back: out = x0 * xw + bias + x  (x already in registers).
    float4 x0a = x0[base + i0];
    float4 x0b = x0[base + i1];
    float4 ba  = bias[i0];
    float4 bb  = bias[i1];

    float4 oa, ob;
    oa.x = fmaf(x0a.x, xw, ba.x + xa.x);
    oa.y = fmaf(x0a.y, xw, ba.y + xa.y);
    oa.z = fmaf(x0a.z, xw, ba.z + xa.z);
    oa.w = fmaf(x0a.w, xw, ba.w + xa.w);
    ob.x = fmaf(x0b.x, xw, bb.x + xb.x);
    ob.y = fmaf(x0b.y, xw, bb.y + xb.y);
    ob.z = fmaf(x0b.z, xw, bb.z + xb.z);
    ob.w = fmaf(x0b.w, xw, bb.w + xb.w);

    out[base + i0] = oa;
    out[base + i1] = ob;
}

extern "C" void kernel_launch(void* const* d_in, const int* in_sizes, int n_in,
                              void* d_out, int out_size)
{
    const float4* x0   = (const float4*)d_in[0];
    const float4* x    = (const float4*)d_in[1];
    const float4* w    = (const float4*)d_in[2];
    const float4* bias = (const float4*)d_in[3];
    float4* out = (float4*)d_out;

    const int rows = in_sizes[0] / F_DIM;  // 16384
    cross_fused_kernel<<<rows, THREADS>>>(x0, x, w, bias, out);
}